// round 11
// baseline (speedup 1.0000x reference)
#include <cuda_runtime.h>
#include <cstdint>

// CSCFCLayer: out[b][n] = sum_{f<64} x[b][(n+f)%C] * kernel[(n+f)%C][n] + bias[n]
// B=128, C=N=8192, F=64, fp32.
//
// v11 = v10 (band-trimmed m16n8k8 tf32, 1024 thr, grid 128) +
//  - direct-STG epilogue (C frags are sector-perfect as STG.64): no os smem,
//    no reload, one less barrier; bias prefetched to regs.
//  - Bs relaid as [k][n] stride 72: fill uses one STS.128 per float4 (was 4x STS.32);
//    mainloop B LDS banks 8*tg+g -> conflict-free.
//  - single __syncthreads in the whole kernel.

#define CDIM 8192
#define NDIM 8192
#define NT 64
#define THREADS 1024
#define ASTRIDE 132
#define BSTRIDE 72             // words per Bs row ([k][n] layout)
#define A_FLOATS (128 * ASTRIDE)
#define SMEM_NEED ((A_FLOATS + 128 * BSTRIDE) * 4)

__device__ __forceinline__ uint32_t f2tf(float f) {
    uint32_t r;
    asm("cvt.rna.tf32.f32 %0, %1;" : "=r"(r) : "f"(f));
    return r;
}

__device__ __forceinline__ void mma_tf32(float* c,
                                         uint32_t a0, uint32_t a1,
                                         uint32_t a2, uint32_t a3,
                                         uint32_t b0, uint32_t b1) {
    asm volatile(
        "mma.sync.aligned.m16n8k8.row.col.f32.tf32.tf32.f32 "
        "{%0,%1,%2,%3}, {%4,%5,%6,%7}, {%8,%9}, {%0,%1,%2,%3};"
        : "+f"(c[0]), "+f"(c[1]), "+f"(c[2]), "+f"(c[3])
        : "r"(a0), "r"(a1), "r"(a2), "r"(a3), "r"(b0), "r"(b1));
}

extern "C" __global__ void __launch_bounds__(THREADS, 1)
cscfc_mma_kernel(const float* __restrict__ x,
                 const float* __restrict__ w,
                 const float* __restrict__ bias,
                 float* __restrict__ out)
{
    extern __shared__ float sm[];
    float* As = sm;               // [128 b][ASTRIDE] raw fp32 x window
    float* Bs = sm + A_FLOATS;    // [128 k][BSTRIDE] banded tf32 weights, [k][n]

    const int tid  = threadIdx.x;
    const int lane = tid & 31;
    const int wid  = tid >> 5;
    const int n0   = blockIdx.x * NT;

    const int mw = wid & 7;       // row group (16 rows)
    const int nw = wid >> 3;      // col group (16 cols)
    const int g  = lane >> 2;     // 0..7
    const int tg = lane & 3;      // 0..3

    // ---- A fill: raw x window via 16B cp.async (4/thread, one group). ----
    {
        const unsigned as_u = (unsigned)__cvta_generic_to_shared(As);
        const int b = tid >> 3;
        const int q = tid & 7;
#pragma unroll
        for (int kc = 0; kc < 4; ++kc) {
            const int col = kc * 32 + q * 4;
            const int c = (n0 + col) & (CDIM - 1);
            const unsigned dst = as_u + (unsigned)(b * ASTRIDE + col) * 4u;
            const float* src = x + (size_t)b * CDIM + c;
            asm volatile("cp.async.cg.shared.global [%0], [%1], 16;"
                         :: "r"(dst), "l"(src) : "memory");
        }
        asm volatile("cp.async.commit_group;" ::: "memory");
    }

    // ---- bias prefetch: thread's 4 output cols. ----
    const float2 bz0 = *(const float2*)(bias + n0 + nw * 16 + tg * 2);
    const float2 bz1 = *(const float2*)(bias + n0 + nw * 16 + 8 + tg * 2);

    // ---- B fill: Bs[cl][n] = tf32(kernel[(n0+cl)%C][n0+n]) banded;
    //      predicated LDG skips all-out-of-band float4s; one STS.128 each. ----
#pragma unroll
    for (int it = 0; it < 2; ++it) {
        const int idx = tid + it * THREADS;
        const int cl = idx >> 4;
        const int nb = (idx & 15) * 4;
        const int r  = (n0 + cl) & (CDIM - 1);
        const bool va = (cl >= nb) && (cl <= nb + 66);
        const float4 wv = va ? *(const float4*)(w + (size_t)r * NDIM + n0 + nb)
                             : make_float4(0.f, 0.f, 0.f, 0.f);
        uint4 st;
        st.x = ((unsigned)(cl - nb)     < 64u) ? f2tf(wv.x) : 0u;
        st.y = ((unsigned)(cl - nb - 1) < 64u) ? f2tf(wv.y) : 0u;
        st.z = ((unsigned)(cl - nb - 2) < 64u) ? f2tf(wv.z) : 0u;
        st.w = ((unsigned)(cl - nb - 3) < 64u) ? f2tf(wv.w) : 0u;
        *(uint4*)&Bs[cl * BSTRIDE + nb] = st;
    }
    asm volatile("cp.async.wait_group 0;" ::: "memory");
    __syncthreads();   // the only barrier

    // ---- Mainloop: warp (mw, nw): rows mw*16..+15, cols nw*16..+15,
    //      k = 16nw .. 16nw+79 (band-trimmed, 10 k8-steps). ----
    float acc[2][4] = {{0.f, 0.f, 0.f, 0.f}, {0.f, 0.f, 0.f, 0.f}};

    const float*    Ap = As + (mw * 16 + g) * ASTRIDE + tg + nw * 16;
    const uint32_t* Bq = (const uint32_t*)Bs + (nw * 16 + tg) * BSTRIDE + nw * 16 + g;

#pragma unroll
    for (int s = 0; s < 10; ++s) {
        const int k0 = s * 8;
        const uint32_t a0 = __float_as_uint(Ap[k0]);                // raw bits = tf32 trunc
        const uint32_t a1 = __float_as_uint(Ap[8 * ASTRIDE + k0]);
        const uint32_t a2 = __float_as_uint(Ap[k0 + 4]);
        const uint32_t a3 = __float_as_uint(Ap[8 * ASTRIDE + k0 + 4]);
        const uint32_t b0 = Bq[k0 * BSTRIDE];
        const uint32_t b1 = Bq[(k0 + 4) * BSTRIDE];
        const uint32_t b2 = Bq[k0 * BSTRIDE + 8];
        const uint32_t b3 = Bq[(k0 + 4) * BSTRIDE + 8];
        mma_tf32(acc[0], a0, a1, a2, a3, b0, b1);
        mma_tf32(acc[1], a0, a1, a2, a3, b2, b3);
    }

    // ---- Epilogue: direct STG.64 (8 full sectors per warp-store) + bias. ----
    {
        const int row = mw * 16 + g;
        const int c0  = n0 + nw * 16 + tg * 2;
        float* o0 = out + (size_t)row * NDIM + c0;
        float* o1 = out + (size_t)(row + 8) * NDIM + c0;
        *(float2*)o0       = make_float2(acc[0][0] + bz0.x, acc[0][1] + bz0.y);
        *(float2*)o1       = make_float2(acc[0][2] + bz0.x, acc[0][3] + bz0.y);
        *(float2*)(o0 + 8) = make_float2(acc[1][0] + bz1.x, acc[1][1] + bz1.y);
        *(float2*)(o1 + 8) = make_float2(acc[1][2] + bz1.x, acc[1][3] + bz1.y);
    }
}

extern "C" void kernel_launch(void* const* d_in, const int* in_sizes, int n_in,
                              void* d_out, int out_size) {
    const float* x    = (const float*)d_in[0];
    const float* w    = (const float*)d_in[1];
    const float* bias = (const float*)d_in[2];
    float* out        = (float*)d_out;

    cudaFuncSetAttribute(cscfc_mma_kernel,
                         cudaFuncAttributeMaxDynamicSharedMemorySize, SMEM_NEED);
    cscfc_mma_kernel<<<NDIM / NT, THREADS, SMEM_NEED>>>(x, w, bias, out);
}

// round 12
// speedup vs baseline: 1.0037x; 1.0037x over previous
#include <cuda_runtime.h>
#include <cstdint>

// CSCFCLayer: out[b][n] = sum_{f<64} x[b][(n+f)%C] * kernel[(n+f)%C][n] + bias[n]
// B=128, C=N=8192, F=64, fp32.
//
// v12 = v11 halved: BT=64 batches/CTA, 512 thr, grid 256, 2 independent CTAs/SM.
// Tests phase-desync: two barrier domains per SM so one CTA's fill/epilogue
// overlaps the sibling's mainloop. Per-warp work identical to v11.
//  - A [64][132] raw fp32 x window (cp.async, 1 group); Bs [128][72] banded tf32 [k][n].
//  - 16 warps: (mw 0..3, nw 0..3), 16 rows x 16 cols, k8 = 2nw .. 2nw+9 (band-trimmed).
//  - One __syncthreads; direct STG.64 epilogue + reg-prefetched bias.

#define CDIM 8192
#define NDIM 8192
#define NT 64
#define BT 64
#define THREADS 512
#define ASTRIDE 132
#define BSTRIDE 72
#define A_FLOATS (BT * ASTRIDE)
#define SMEM_NEED ((A_FLOATS + 128 * BSTRIDE) * 4)

__device__ __forceinline__ uint32_t f2tf(float f) {
    uint32_t r;
    asm("cvt.rna.tf32.f32 %0, %1;" : "=r"(r) : "f"(f));
    return r;
}

__device__ __forceinline__ void mma_tf32(float* c,
                                         uint32_t a0, uint32_t a1,
                                         uint32_t a2, uint32_t a3,
                                         uint32_t b0, uint32_t b1) {
    asm volatile(
        "mma.sync.aligned.m16n8k8.row.col.f32.tf32.tf32.f32 "
        "{%0,%1,%2,%3}, {%4,%5,%6,%7}, {%8,%9}, {%0,%1,%2,%3};"
        : "+f"(c[0]), "+f"(c[1]), "+f"(c[2]), "+f"(c[3])
        : "r"(a0), "r"(a1), "r"(a2), "r"(a3), "r"(b0), "r"(b1));
}

extern "C" __global__ void __launch_bounds__(THREADS, 2)
cscfc_mma_kernel(const float* __restrict__ x,
                 const float* __restrict__ w,
                 const float* __restrict__ bias,
                 float* __restrict__ out)
{
    extern __shared__ float sm[];
    float* As = sm;               // [64 b][ASTRIDE] raw fp32 x window
    float* Bs = sm + A_FLOATS;    // [128 k][BSTRIDE] banded tf32 weights, [k][n]

    const int tid  = threadIdx.x;
    const int lane = tid & 31;
    const int wid  = tid >> 5;
    const int tile = blockIdx.x >> 1;
    const int bh   = blockIdx.x & 1;
    const int n0   = tile * NT;
    const int b0   = bh * BT;

    const int mw = wid & 3;       // row group (16 rows of 64)
    const int nw = wid >> 2;      // col group (16 cols)
    const int g  = lane >> 2;     // 0..7
    const int tg = lane & 3;      // 0..3

    // ---- A fill: raw x window via 16B cp.async (4/thread, one group). ----
    {
        const unsigned as_u = (unsigned)__cvta_generic_to_shared(As);
        const int b = tid >> 3;           // 0..63
        const int q = tid & 7;
#pragma unroll
        for (int kc = 0; kc < 4; ++kc) {
            const int col = kc * 32 + q * 4;
            const int c = (n0 + col) & (CDIM - 1);
            const unsigned dst = as_u + (unsigned)(b * ASTRIDE + col) * 4u;
            const float* src = x + (size_t)(b0 + b) * CDIM + c;
            asm volatile("cp.async.cg.shared.global [%0], [%1], 16;"
                         :: "r"(dst), "l"(src) : "memory");
        }
        asm volatile("cp.async.commit_group;" ::: "memory");
    }

    // ---- bias prefetch: thread's 4 output cols. ----
    const float2 bz0 = *(const float2*)(bias + n0 + nw * 16 + tg * 2);
    const float2 bz1 = *(const float2*)(bias + n0 + nw * 16 + 8 + tg * 2);

    // ---- B fill: Bs[cl][n] = tf32(kernel[(n0+cl)%C][n0+n]) banded; predicated
    //      LDG skips all-out-of-band float4s; one STS.128 each. ----
#pragma unroll
    for (int it = 0; it < 4; ++it) {
        const int idx = tid + it * THREADS;
        const int cl = idx >> 4;
        const int nb = (idx & 15) * 4;
        const int r  = (n0 + cl) & (CDIM - 1);
        const bool va = (cl >= nb) && (cl <= nb + 66);
        const float4 wv = va ? *(const float4*)(w + (size_t)r * NDIM + n0 + nb)
                             : make_float4(0.f, 0.f, 0.f, 0.f);
        uint4 st;
        st.x = ((unsigned)(cl - nb)     < 64u) ? f2tf(wv.x) : 0u;
        st.y = ((unsigned)(cl - nb - 1) < 64u) ? f2tf(wv.y) : 0u;
        st.z = ((unsigned)(cl - nb - 2) < 64u) ? f2tf(wv.z) : 0u;
        st.w = ((unsigned)(cl - nb - 3) < 64u) ? f2tf(wv.w) : 0u;
        *(uint4*)&Bs[cl * BSTRIDE + nb] = st;
    }
    asm volatile("cp.async.wait_group 0;" ::: "memory");
    __syncthreads();   // the only barrier

    // ---- Mainloop: warp (mw, nw): rows mw*16..+15, cols nw*16..+15,
    //      k = 16nw .. 16nw+79 (band-trimmed, 10 k8-steps). ----
    float acc[2][4] = {{0.f, 0.f, 0.f, 0.f}, {0.f, 0.f, 0.f, 0.f}};

    const float*    Ap = As + (mw * 16 + g) * ASTRIDE + tg + nw * 16;
    const uint32_t* Bq = (const uint32_t*)Bs + (nw * 16 + tg) * BSTRIDE + nw * 16 + g;

#pragma unroll
    for (int s = 0; s < 10; ++s) {
        const int k0 = s * 8;
        const uint32_t a0 = __float_as_uint(Ap[k0]);                // raw bits = tf32 trunc
        const uint32_t a1 = __float_as_uint(Ap[8 * ASTRIDE + k0]);
        const uint32_t a2 = __float_as_uint(Ap[k0 + 4]);
        const uint32_t a3 = __float_as_uint(Ap[8 * ASTRIDE + k0 + 4]);
        const uint32_t b0 = Bq[k0 * BSTRIDE];
        const uint32_t b1 = Bq[(k0 + 4) * BSTRIDE];
        const uint32_t b2 = Bq[k0 * BSTRIDE + 8];
        const uint32_t b3 = Bq[(k0 + 4) * BSTRIDE + 8];
        mma_tf32(acc[0], a0, a1, a2, a3, b0, b1);
        mma_tf32(acc[1], a0, a1, a2, a3, b2, b3);
    }

    // ---- Epilogue: direct STG.64 + bias. ----
    {
        const int row = b0 + mw * 16 + g;
        const int c0  = n0 + nw * 16 + tg * 2;
        float* o0 = out + (size_t)row * NDIM + c0;
        float* o1 = out + (size_t)(row + 8) * NDIM + c0;
        *(float2*)o0       = make_float2(acc[0][0] + bz0.x, acc[0][1] + bz0.y);
        *(float2*)o1       = make_float2(acc[0][2] + bz0.x, acc[0][3] + bz0.y);
        *(float2*)(o0 + 8) = make_float2(acc[1][0] + bz1.x, acc[1][1] + bz1.y);
        *(float2*)(o1 + 8) = make_float2(acc[1][2] + bz1.x, acc[1][3] + bz1.y);
    }
}

extern "C" void kernel_launch(void* const* d_in, const int* in_sizes, int n_in,
                              void* d_out, int out_size) {
    const float* x    = (const float*)d_in[0];
    const float* w    = (const float*)d_in[1];
    const float* bias = (const float*)d_in[2];
    float* out        = (float*)d_out;

    cudaFuncSetAttribute(cscfc_mma_kernel,
                         cudaFuncAttributeMaxDynamicSharedMemorySize, SMEM_NEED);
    cscfc_mma_kernel<<<2 * (NDIM / NT), THREADS, SMEM_NEED>>>(x, w, bias, out);
}